// round 7
// baseline (speedup 1.0000x reference)
#include <cuda_runtime.h>
#include <math.h>
#include <stdint.h>

#define B_ROWS 4096
#define DIM    512
#define NCLS   31
#define NTOT   8192
#define NT     32        // 4096/128 tiles per side
#define TRI    528       // NT*(NT+1)/2

typedef unsigned long long ull;

// ---------------- device scratch ----------------
__device__ double g_sumsq;
__device__ double g_acc[3];
__device__ float  g_S[DIM];
__device__ float  g_sq[NTOT];
__device__ int    g_scount[NCLS];
__device__ int    g_tcount[NCLS];
__device__ float  g_tcolsum[NCLS];
__device__ float  g_css[NCLS];
__device__ float  g_cst[NCLS];
__device__ float  g_invts[NCLS];
__device__ __align__(16) float g_u[B_ROWS * 32];
__device__ float  g_c[5];
__device__ float  g_scale;
__device__ float  g_lamb;
// precomputed TT weights (scale * <u_i,u_j>), upper-triangle tiles, [tri][128][128]
__device__ __align__(16) float g_wtt[TRI * 128 * 128];

// ---------------- init ----------------
__global__ void k_init() {
    int t = threadIdx.x;
    if (t == 0) g_sumsq = 0.0;
    if (t < 3) g_acc[t] = 0.0;
    if (t < NCLS) { g_scount[t] = 0; g_tcount[t] = 0; g_tcolsum[t] = 0.f; }
    if (t < DIM) g_S[t] = 0.f;
}

// ---------------- row squared norms ----------------
__global__ void k_sq(const float* __restrict__ src, const float* __restrict__ tgt) {
    int w = (blockIdx.x * blockDim.x + threadIdx.x) >> 5;
    int lane = threadIdx.x & 31;
    if (w >= NTOT) return;
    const float* row = (w < B_ROWS) ? (src + (size_t)w * DIM)
                                    : (tgt + (size_t)(w - B_ROWS) * DIM);
    float s = 0.f;
    for (int k = lane; k < DIM; k += 32) { float v = row[k]; s = fmaf(v, v, s); }
    #pragma unroll
    for (int o = 16; o; o >>= 1) s += __shfl_xor_sync(0xffffffffu, s, o);
    if (lane == 0) { g_sq[w] = s; atomicAdd(&g_sumsq, (double)s); }
}

// ---------------- column sums ----------------
__global__ void k_colsum(const float* __restrict__ src, const float* __restrict__ tgt) {
    int d = threadIdx.x;
    int b = blockIdx.x;
    float s = 0.f;
    int r0 = b * 128;
    for (int r = r0; r < r0 + 128; r++)
        s += src[(size_t)r * DIM + d] + tgt[(size_t)r * DIM + d];
    atomicAdd(&g_S[d], s);
}

// ---------------- class stats ----------------
__global__ void k_stats(const int* __restrict__ lbl, const float* __restrict__ logits) {
    int b = blockIdx.x;
    int t = threadIdx.x;
    int i = b * 256 + t;
    atomicAdd(&g_scount[lbl[i]], 1);
    const float* row = logits + (size_t)i * NCLS;
    float mv = row[0]; int mi = 0;
    #pragma unroll
    for (int c = 1; c < NCLS; c++) { float v = row[c]; if (v > mv) { mv = v; mi = c; } }
    atomicAdd(&g_tcount[mi], 1);
    if (t < NCLS) {
        float s = 0.f;
        for (int r = 0; r < 256; r++) s += logits[(size_t)(b * 256 + r) * NCLS + t];
        atomicAdd(&g_tcolsum[t], s);
    }
}

// ---------------- finalize ----------------
__global__ void k_finalize(const int* __restrict__ curr_iter) {
    __shared__ double sred[512];
    __shared__ float  sm[NCLS];
    __shared__ float  sscale;
    int t = threadIdx.x;
    double v = (double)g_S[t];
    sred[t] = v * v;
    __syncthreads();
    for (int o = 256; o; o >>= 1) { if (t < o) sred[t] += sred[t + o]; __syncthreads(); }
    if (t < NCLS) sm[t] = (g_scount[t] > 0 && g_tcount[t] > 0) ? 1.f : 0.f;
    __syncthreads();
    if (t == 0) {
        float cnt = 0.f;
        for (int c = 0; c < NCLS; c++) cnt += sm[c];
        sscale = (cnt > 0.f) ? 1.f / fmaxf(cnt, 1.f) : 0.f;
        g_scale = sscale;
    }
    __syncthreads();
    if (t < NCLS) {
        float m = sm[t];
        int sc = g_scount[t];
        float css = 0.f, cst = 0.f;
        if (sc > 0) { float fc = (float)sc; css = m * sscale / (fc * fc); cst = m * sscale / fc; }
        g_css[t] = css; g_cst[t] = cst;
        float ts = g_tcolsum[t]; if (ts == 0.f) ts = 100.f;
        g_invts[t] = m / ts;
    }
    if (t == 0) {
        double sumL2 = 2.0 * (double)NTOT * g_sumsq - 2.0 * sred[0];
        double bw = sumL2 / ((double)NTOT * (double)NTOT - (double)NTOT);
        bw = bw / 4.0;
        for (int i = 0; i < 5; i++)
            g_c[i] = (float)(-1.4426950408889634 / (bw * (double)(1 << i)));
        double p = (double)curr_iter[0] / 1000.0;
        g_lamb = (float)(2.0 / (1.0 + exp(-p)) - 1.0);
    }
}

// ---------------- masked normalized target logits ----------------
__global__ void k_u(const float* __restrict__ logits) {
    int i = blockIdx.x * blockDim.x + threadIdx.x;
    if (i >= B_ROWS) return;
    #pragma unroll
    for (int c = 0; c < NCLS; c++)
        g_u[i * 32 + c] = logits[(size_t)i * NCLS + c] * g_invts[c];
    g_u[i * 32 + 31] = 0.f;
}

// ---------------- precompute TT weight tiles: scale * U U^T ----------------
__global__ __launch_bounds__(256, 2)
void k_wtt() {
    __shared__ float Us[128][33];
    __shared__ float Ut[128][33];
    int bid = blockIdx.x;     // tri index
    int r = 0, b = bid;
    while (b >= NT - r) { b -= NT - r; r++; }
    int ti = r, tj = r + b;
    int gi0 = ti * 128, gj0 = tj * 128;
    int t = threadIdx.x;
    int tx = t & 15, ty = t >> 4;

    for (int idx = t; idx < 4096; idx += 256) {
        int row = idx >> 5, c = idx & 31;
        Us[row][c] = g_u[(size_t)(gi0 + row) * 32 + c];
        Ut[row][c] = g_u[(size_t)(gj0 + row) * 32 + c];
    }
    __syncthreads();

    float acc[8][8];
    #pragma unroll
    for (int i = 0; i < 8; i++)
        #pragma unroll
        for (int j = 0; j < 8; j++) acc[i][j] = 0.f;

    #pragma unroll 1
    for (int c = 0; c < NCLS; c++) {
        float a[8], bb[8];
        #pragma unroll
        for (int i = 0; i < 8; i++) a[i] = Us[ty * 8 + i][c];
        #pragma unroll
        for (int j = 0; j < 8; j++) bb[j] = Ut[tx * 8 + j][c];
        #pragma unroll
        for (int i = 0; i < 8; i++)
            #pragma unroll
            for (int j = 0; j < 8; j++)
                acc[i][j] = fmaf(a[i], bb[j], acc[i][j]);
    }

    float scale = g_scale;
    float* W = g_wtt + (size_t)bid * 16384;
    #pragma unroll
    for (int i = 0; i < 8; i++) {
        int il = ty * 8 + i;
        float4 v0 = make_float4(acc[i][0]*scale, acc[i][1]*scale, acc[i][2]*scale, acc[i][3]*scale);
        float4 v1 = make_float4(acc[i][4]*scale, acc[i][5]*scale, acc[i][6]*scale, acc[i][7]*scale);
        *(float4*)(W + il * 128 + tx * 8 + 0) = v0;
        *(float4*)(W + il * 128 + tx * 8 + 4) = v1;
    }
}

// ---------------- helpers ----------------
__device__ __forceinline__ float ex2f(float x) {
    float r; asm("ex2.approx.ftz.f32 %0, %1;" : "=f"(r) : "f"(x)); return r;
}
#define FFMA2(d, a, b) \
    asm("fma.rn.f32x2 %0, %1, %2, %0;" : "+l"(d) : "l"(a), "l"(b))
#define PACK2(d, x) \
    asm("mov.b64 %0, {%1, %1};" : "=l"(d) : "f"(x))
#define UNPACK2(lo, hi, v) \
    asm("mov.b64 {%0, %1}, %2;" : "=f"(lo), "=f"(hi) : "l"(v))

// ---------------- main fused GEMM + kernel-weight epilogue ----------------
__global__ __launch_bounds__(256, 2)
void k_main(const float* __restrict__ src, const float* __restrict__ tgt,
            const int* __restrict__ slabel) {
    __shared__ float As[2][8][256];     // DUPLICATED: As[s][k][2*row]=As[s][k][2*row+1]=v
    __shared__ float BP[2][8][128];     // pair-swizzled (ull idx = jp*16 + tx)
    __shared__ float sqI[128], sqJ[128];
    __shared__ int   Li[128], Lj[128];
    __shared__ float s_css[32], s_cst[32];
    __shared__ float UjT[32][128];      // type==2 only: [class][j]

    int bid = blockIdx.x;
    int type, ti, tj, triq = 0;
    if (bid < TRI) { type = 0; }
    else if (bid < 2 * TRI) { type = 1; bid -= TRI; }
    else { type = 2; bid -= 2 * TRI; }
    if (type < 2) {
        int r = 0, b = bid;
        while (b >= NT - r) { b -= NT - r; r++; }
        ti = r; tj = r + b; triq = bid;
    } else { ti = bid >> 5; tj = bid & 31; }

    const float* Xi = (type == 1) ? tgt : src;
    const float* Xj = (type == 0) ? src : tgt;
    int gi0 = ti * 128, gj0 = tj * 128;

    int t = threadIdx.x;
    int tx = t & 15, ty = t >> 4;
    int lr = t >> 1, lc = (t & 1) << 2;

    const float* pa = Xi + (size_t)(gi0 + lr) * DIM + lc;
    const float* pb = Xj + (size_t)(gj0 + lr) * DIM + lc;

    // pair-swizzle store index for B (depends only on lr)
    int pi_ = lr >> 1;
    int bfi = ((pi_ & 3) * 16 + (pi_ >> 2)) * 2 + (lr & 1);

    // ---- small-table loads ----
    if (t < 128) {
        sqI[t] = g_sq[((type == 1) ? B_ROWS : 0) + gi0 + t];
        sqJ[t] = g_sq[((type == 0) ? 0 : B_ROWS) + gj0 + t];
        if (type != 1) Li[t] = slabel[gi0 + t];
        if (type == 0) Lj[t] = slabel[gj0 + t];
    }
    if (t < NCLS) { s_css[t] = g_css[t]; s_cst[t] = g_cst[t]; }
    if (type == 2) {
        for (int idx = t; idx < 4096; idx += 256) {
            int c = idx >> 7, j = idx & 127;
            UjT[c][j] = g_u[(size_t)(gj0 + j) * 32 + c];
        }
    }

    // ---- prefetch first chunk ----
    float4 a_nx = *(const float4*)pa;
    float4 b_nx = *(const float4*)pb;

    ull acc2[8][4];
    #pragma unroll
    for (int i = 0; i < 8; i++)
        #pragma unroll
        for (int j = 0; j < 4; j++) acc2[i][j] = 0ull;

    #pragma unroll 1
    for (int c = 0; c < 64; c++) {
        int s = c & 1;
        // store current chunk: A duplicated (PACK2 + STS.64), B pair-swizzled
        {
            ull* arow0 = (ull*)&As[s][lc + 0][0];
            ull* arow1 = (ull*)&As[s][lc + 1][0];
            ull* arow2 = (ull*)&As[s][lc + 2][0];
            ull* arow3 = (ull*)&As[s][lc + 3][0];
            ull p0, p1, p2, p3;
            PACK2(p0, a_nx.x); PACK2(p1, a_nx.y);
            PACK2(p2, a_nx.z); PACK2(p3, a_nx.w);
            arow0[lr] = p0; arow1[lr] = p1; arow2[lr] = p2; arow3[lr] = p3;
            BP[s][lc + 0][bfi] = b_nx.x; BP[s][lc + 1][bfi] = b_nx.y;
            BP[s][lc + 2][bfi] = b_nx.z; BP[s][lc + 3][bfi] = b_nx.w;
        }
        __syncthreads();           // single barrier per chunk (double-buffer safe)
        // prefetch next chunk
        if (c < 63) {
            a_nx = *(const float4*)(pa + (c + 1) * 8);
            b_nx = *(const float4*)(pb + (c + 1) * 8);
        }
        #pragma unroll
        for (int kk = 0; kk < 8; kk++) {
            const ull* brow = (const ull*)&BP[s][kk][0];
            ull bp[4];
            #pragma unroll
            for (int jp = 0; jp < 4; jp++) bp[jp] = brow[jp * 16 + tx];
            const ulonglong2* arow = (const ulonglong2*)&As[s][kk][ty * 16];
            ull aa[8];
            #pragma unroll
            for (int ip = 0; ip < 4; ip++) {
                ulonglong2 av = arow[ip];
                aa[2 * ip] = av.x; aa[2 * ip + 1] = av.y;
            }
            #pragma unroll
            for (int i = 0; i < 8; i++)
                #pragma unroll
                for (int jp = 0; jp < 4; jp++)
                    FFMA2(acc2[i][jp], aa[i], bp[jp]);
        }
    }

    // ---- epilogue ----
    float c4 = g_c[4];
    float part = 0.f;

    if (type == 0) {
        #pragma unroll
        for (int ii = 0; ii < 8; ii++) {
            int il = ty * 8 + ii;
            float si = sqI[il];
            int li = Li[il];
            float wcls = s_css[li];
            #pragma unroll
            for (int jp = 0; jp < 4; jp++) {
                float d0, d1;
                UNPACK2(d0, d1, acc2[ii][jp]);
                #pragma unroll
                for (int h = 0; h < 2; h++) {
                    int jl = tx * 8 + 2 * jp + h;
                    float dot = h ? d1 : d0;
                    float L2 = fmaxf(fmaf(-2.f, dot, si + sqJ[jl]), 0.f);
                    float e4 = ex2f(L2 * c4);
                    float e3 = e4 * e4, e2 = e3 * e3, e1 = e2 * e2, e0 = e1 * e1;
                    float ks = ((e0 + e1) + (e2 + e3)) + e4;
                    float w = (li == Lj[jl]) ? wcls : 0.f;
                    part = fmaf(w, ks, part);
                }
            }
        }
    } else if (type == 1) {
        const float4* Wt = (const float4*)(g_wtt + (size_t)triq * 16384);
        int base = (ty * 8) * 32 + tx * 2;
        float4 wa = Wt[base], wb = Wt[base + 1];
        #pragma unroll
        for (int ii = 0; ii < 8; ii++) {
            int il = ty * 8 + ii;
            float si = sqI[il];
            float wv[8] = { wa.x, wa.y, wa.z, wa.w, wb.x, wb.y, wb.z, wb.w };
            if (ii < 7) { wa = Wt[base + (ii + 1) * 32]; wb = Wt[base + (ii + 1) * 32 + 1]; }
            #pragma unroll
            for (int jp = 0; jp < 4; jp++) {
                float d0, d1;
                UNPACK2(d0, d1, acc2[ii][jp]);
                #pragma unroll
                for (int h = 0; h < 2; h++) {
                    int jj = 2 * jp + h;
                    int jl = tx * 8 + jj;
                    float dot = h ? d1 : d0;
                    float L2 = fmaxf(fmaf(-2.f, dot, si + sqJ[jl]), 0.f);
                    float e4 = ex2f(L2 * c4);
                    float e3 = e4 * e4, e2 = e3 * e3, e1 = e2 * e2, e0 = e1 * e1;
                    float ks = ((e0 + e1) + (e2 + e3)) + e4;
                    part = fmaf(wv[jj], ks, part);
                }
            }
        }
    } else {
        #pragma unroll
        for (int ii = 0; ii < 8; ii++) {
            int il = ty * 8 + ii;
            float si = sqI[il];
            int li = Li[il];
            float wc = s_cst[li];
            #pragma unroll
            for (int jp = 0; jp < 4; jp++) {
                float d0, d1;
                UNPACK2(d0, d1, acc2[ii][jp]);
                #pragma unroll
                for (int h = 0; h < 2; h++) {
                    int jl = tx * 8 + 2 * jp + h;
                    float dot = h ? d1 : d0;
                    float L2 = fmaxf(fmaf(-2.f, dot, si + sqJ[jl]), 0.f);
                    float e4 = ex2f(L2 * c4);
                    float e3 = e4 * e4, e2 = e3 * e3, e1 = e2 * e2, e0 = e1 * e1;
                    float ks = ((e0 + e1) + (e2 + e3)) + e4;
                    part = fmaf(wc * UjT[li][jl], ks, part);
                }
            }
        }
    }

    #pragma unroll
    for (int o = 16; o; o >>= 1) part += __shfl_xor_sync(0xffffffffu, part, o);
    if ((t & 31) == 0) {
        double f = (type < 2 && ti != tj) ? 2.0 : 1.0;
        atomicAdd(&g_acc[type], f * (double)part);
    }
}

// ---------------- output ----------------
__global__ void k_out(float* out) {
    out[0] = (float)(g_lamb * (g_acc[0] + g_acc[1] - 2.0 * g_acc[2]));
}

extern "C" void kernel_launch(void* const* d_in, const int* in_sizes, int n_in,
                              void* d_out, int out_size) {
    const float* src    = (const float*)d_in[0];
    const float* tgt    = (const float*)d_in[1];
    const int*   lbl    = (const int*)d_in[2];
    const float* logits = (const float*)d_in[3];
    const int*   iter   = (const int*)d_in[4];
    float* out = (float*)d_out;

    k_init<<<1, 512>>>();
    k_sq<<<(NTOT * 32) / 256, 256>>>(src, tgt);
    k_colsum<<<32, 512>>>(src, tgt);
    k_stats<<<16, 256>>>(lbl, logits);
    k_finalize<<<1, 512>>>(iter);
    k_u<<<16, 256>>>(logits);
    k_wtt<<<TRI, 256>>>();
    k_main<<<2 * TRI + NT * NT, 256>>>(src, tgt, lbl);
    k_out<<<1, 1>>>(out);
}